// round 1
// baseline (speedup 1.0000x reference)
#include <cuda_runtime.h>
#include <cstdint>

// ---------------------------------------------------------------------------
// FeatureIntegration: gather+pad -> SE gate -> big GEMM (32768x1536 @ 1536x256)
// Round 0 baseline: fp32 with packed fma.rn.f32x2 (2x FFMA issue rate).
// ---------------------------------------------------------------------------

#define N_ENT    32
#define C_DIM    64
#define OUT_DIM  256
#define LEN_M    16
#define LEN_L    8
#define T_EFF    24                 // effective (non-zero) positions per entity
#define K_EFF    (T_EFF * C_DIM)    // 1536
#define B_SZ     1024
#define ROWS_TOT (B_SZ * N_ENT)     // 32768

#define TILE_ROWS 64
#define PA 68     // As row pitch (floats): mult of 4 -> STS.128 aligned, reads are broadcast
#define PW 260    // Ws row pitch (floats): mult of 4 -> STS.128 aligned, LDS.64 reads contiguous

// Scratch (no cudaMalloc allowed)
__device__ float g_gate[(size_t)ROWS_TOT * C_DIM];   // 8.4 MB
__device__ float g_wt[(size_t)K_EFF * OUT_DIM];      // 1.5 MB  (compacted, transposed W)

// ---------------------------------------------------------------------------
// Kernel 1: SE gate.  gate[bn][c] = sigmoid( relu(pooled @ w1^T) @ w2^T )
// pooled[c] = (sum_{t<16} xm + sum_{t<8} xl) / 32   (padded rows are zero)
// 256 threads = 4 groups of 64; thread c of a group owns channel c.
// ---------------------------------------------------------------------------
__global__ void gate_kernel(const float* __restrict__ xm,
                            const float* __restrict__ xl,
                            const float* __restrict__ w1,   // (4,64) row-major
                            const float* __restrict__ w2)   // (64,4) row-major
{
    int g  = threadIdx.x >> 6;
    int c  = threadIdx.x & 63;
    int bn = blockIdx.x * 4 + g;
    int b  = bn >> 5;
    int n  = bn & 31;

    const float* pm = xm + ((size_t)(b * (N_ENT * LEN_M) + n * LEN_M)) * C_DIM + c;
    float s = 0.f;
#pragma unroll
    for (int t = 0; t < LEN_M; t++) s += pm[t * C_DIM];
    const float* pl = xl + ((size_t)(b * (N_ENT * LEN_L) + n * LEN_L)) * C_DIM + c;
#pragma unroll
    for (int t = 0; t < LEN_L; t++) s += pl[t * C_DIM];
    float pooled = s * (1.0f / 32.0f);

    __shared__ float sp[4][C_DIM];
    __shared__ float sh[4][4];
    sp[g][c] = pooled;
    __syncthreads();

    if (c < 4) {
        float h = 0.f;
#pragma unroll
        for (int i = 0; i < C_DIM; i++) h += sp[g][i] * w1[c * C_DIM + i];
        sh[g][c] = fmaxf(h, 0.f);
    }
    __syncthreads();

    float z = 0.f;
#pragma unroll
    for (int r = 0; r < 4; r++) z += sh[g][r] * w2[c * 4 + r];
    float gate = 1.0f / (1.0f + expf(-z));
    g_gate[(size_t)bn * C_DIM + c] = gate;
}

// ---------------------------------------------------------------------------
// Kernel 2: compact + transpose align_w (256 x 2048) -> Wt (1536 x 256).
// Compact index kg = t*64 + c (t<16: metric block, t in 16..23: log block);
// source f = kg + (kg >= 1024 ? 256 : 0)  (skips the 4+4 zero-padded positions).
// Reads coalesced along f; scattered writes are tiny (1.5 MB total).
// ---------------------------------------------------------------------------
__global__ void wprep_kernel(const float* __restrict__ aw)
{
    int idx = blockIdx.x * blockDim.x + threadIdx.x;   // 0 .. 256*1536-1
    int o   = idx / K_EFF;
    int kg  = idx - o * K_EFF;
    int f   = kg + (kg >= 1024 ? 256 : 0);
    g_wt[(size_t)kg * OUT_DIM + o] = aw[(size_t)o * 2048 + f];
}

// ---------------------------------------------------------------------------
// Kernel 3: GEMM.  out[bn][o] = sum_kg A[bn][kg]*Wt[kg][o] + bias[o]
// A[bn][t*64+c] = x_src[b, pos(t), c] * gate[bn][c]   (built in smem per tile)
// CTA: 64 rows x 256 outs, K-tile = 64 (one t).  256 threads.
// Thread (tr=tid/32, tc=tid%32): rows tr*8+i (i<8), cols tc*2 + 64*j + {0,1}.
// Inner loop uses fma.rn.f32x2 (2 FMA/instr). W pairs load directly as b64.
// ---------------------------------------------------------------------------
extern __shared__ float smem_dyn[];

__global__ __launch_bounds__(256, 2)
void gemm_kernel(const float* __restrict__ xm,
                 const float* __restrict__ xl,
                 const float* __restrict__ bias,
                 float* __restrict__ out)
{
    float* As = smem_dyn;                       // 64 * PA
    float* Ws = As + TILE_ROWS * PA;            // 64 * PW
    float* Gs = Ws + 64 * PW;                   // 64 * 64

    const int tid      = threadIdx.x;
    const int row_base = blockIdx.x * TILE_ROWS;
    const int tc = tid & 31;
    const int tr = tid >> 5;

    // Load gates for this CTA's 64 rows (reused across all 24 K-tiles)
#pragma unroll
    for (int i = 0; i < 4; i++) {
        int lin = i * 1024 + tid * 4;
        int r = lin >> 6, c = lin & 63;
        float4 gg = *(const float4*)&g_gate[(size_t)(row_base + r) * C_DIM + c];
        *(float4*)&Gs[r * C_DIM + c] = gg;
    }

    unsigned long long acc[8][4];
#pragma unroll
    for (int i = 0; i < 8; i++)
#pragma unroll
        for (int j = 0; j < 4; j++) acc[i][j] = 0ULL;

    __syncthreads();

    for (int t = 0; t < T_EFF; t++) {
        // ---- load A tile (64 rows x 64 ch), gated, row-major in smem ----
#pragma unroll
        for (int i = 0; i < 4; i++) {
            int lin = i * 1024 + tid * 4;
            int r = lin >> 6, c = lin & 63;
            int bn = row_base + r;
            int b = bn >> 5, n = bn & 31;
            const float* src;
            if (t < LEN_M)
                src = xm + (((size_t)b * (N_ENT * LEN_M) + n * LEN_M + t) * C_DIM + c);
            else
                src = xl + (((size_t)b * (N_ENT * LEN_L) + n * LEN_L + (t - LEN_M)) * C_DIM + c);
            float4 v  = *(const float4*)src;
            float4 gg = *(const float4*)&Gs[r * C_DIM + c];
            v.x *= gg.x; v.y *= gg.y; v.z *= gg.z; v.w *= gg.w;
            *(float4*)&As[r * PA + c] = v;
        }
        // ---- load W tile (64 k x 256 o), k-major in smem ----
        const float* wsrc = g_wt + (size_t)t * 64 * OUT_DIM;
#pragma unroll
        for (int i = 0; i < 16; i++) {
            int lin = i * 1024 + tid * 4;
            int k = lin >> 8, o = lin & 255;
            *(float4*)&Ws[k * PW + o] = *(const float4*)&wsrc[k * OUT_DIM + o];
        }
        __syncthreads();

        // ---- compute: 64 k-steps, processed 2 at a time ----
#pragma unroll 4
        for (int k = 0; k < 64; k += 2) {
            float2 a[8];
#pragma unroll
            for (int i = 0; i < 8; i++)
                a[i] = *(const float2*)&As[(tr * 8 + i) * PA + k];

            unsigned long long w0[4], w1[4];
#pragma unroll
            for (int j = 0; j < 4; j++) {
                w0[j] = *(const unsigned long long*)&Ws[k * PW + tc * 2 + 64 * j];
                w1[j] = *(const unsigned long long*)&Ws[(k + 1) * PW + tc * 2 + 64 * j];
            }
#pragma unroll
            for (int i = 0; i < 8; i++) {
                unsigned long long ax, ay;
                asm("mov.b64 %0, {%1, %1};" : "=l"(ax) : "f"(a[i].x));
                asm("mov.b64 %0, {%1, %1};" : "=l"(ay) : "f"(a[i].y));
#pragma unroll
                for (int j = 0; j < 4; j++) {
                    asm("fma.rn.f32x2 %0, %1, %2, %0;" : "+l"(acc[i][j]) : "l"(ax), "l"(w0[j]));
                    asm("fma.rn.f32x2 %0, %1, %2, %0;" : "+l"(acc[i][j]) : "l"(ay), "l"(w1[j]));
                }
            }
        }
        __syncthreads();
    }

    // ---- epilogue: add bias, store (coalesced float2 per (row, j)) ----
#pragma unroll
    for (int j = 0; j < 4; j++) {
        int col = tc * 2 + 64 * j;
        float2 bb = *(const float2*)&bias[col];
#pragma unroll
        for (int i = 0; i < 8; i++) {
            float lo, hi;
            asm("mov.b64 {%0, %1}, %2;" : "=f"(lo), "=f"(hi) : "l"(acc[i][j]));
            lo += bb.x; hi += bb.y;
            int row = row_base + tr * 8 + i;
            float2 v; v.x = lo; v.y = hi;
            *(float2*)&out[(size_t)row * OUT_DIM + col] = v;
        }
    }
}

// ---------------------------------------------------------------------------
// Launch. Inputs (metadata order): x_metric, x_log, y(unused), se_w1, se_w2,
// align_w, align_b. Output fp32 (1024, 32, 256).
// ---------------------------------------------------------------------------
extern "C" void kernel_launch(void* const* d_in, const int* in_sizes, int n_in,
                              void* d_out, int out_size)
{
    const float* xm = (const float*)d_in[0];
    const float* xl = (const float*)d_in[1];
    const float* w1 = (const float*)d_in[3];
    const float* w2 = (const float*)d_in[4];
    const float* aw = (const float*)d_in[5];
    const float* ab = (const float*)d_in[6];
    float* out = (float*)d_out;

    const int smem_bytes = (TILE_ROWS * PA + 64 * PW + 64 * 64) * (int)sizeof(float); // 100352
    cudaFuncSetAttribute(gemm_kernel, cudaFuncAttributeMaxDynamicSharedMemorySize, smem_bytes);

    gate_kernel<<<ROWS_TOT / 4, 256>>>(xm, xl, w1, w2);
    wprep_kernel<<<(OUT_DIM * K_EFF) / 256, 256>>>(aw);
    gemm_kernel<<<ROWS_TOT / TILE_ROWS, 256, smem_bytes>>>(xm, xl, ab, out);
}

// round 6
// speedup vs baseline: 2.1389x; 2.1389x over previous
#include <cuda_runtime.h>
#include <cstdint>

// ---------------------------------------------------------------------------
// FeatureIntegration: gather+pad -> SE gate -> GEMM (32768x1536 @ 1536x256)
// Round 6: byte-identical resubmit of R5 (never compiled — container flake;
// R4 proved compile errors ARE reported when the container comes up, R0
// proved containers die on an empty stub too -> failures uncorrelated with
// kernel content). mma.sync.m16n8k8.tf32 GEMM, CTA 128x128, 4 warps,
// fragment-permuted conflict-free smem, gate fused into A-tile store.
// ---------------------------------------------------------------------------

#define N_ENT    32
#define C_DIM    64
#define OUT_DIM  256
#define LEN_M    16
#define LEN_L    8
#define B_SZ     1024
#define ROWS_TOT (B_SZ * N_ENT)     // 32768

#define KT_TILES 48                 // 48 K-tiles of 32 floats = K_eff 1536
#define PITCH    36                 // smem row pitch in floats (pad 4)

// smem float offsets
#define SM_AS 0                     // 128 * 36
#define SM_BS 4608                  // 128 * 36
#define SM_GS 9216                  // 128 * 64
#define SM_FLOATS 17408             // 69632 bytes

__device__ float g_gate[(size_t)ROWS_TOT * C_DIM];   // 8.4 MB scratch

__device__ __forceinline__ uint32_t f2tf32(float f) {
    uint32_t r;
    asm("cvt.rna.tf32.f32 %0, %1;" : "=r"(r) : "f"(f));
    return r;
}

__device__ __forceinline__ void mma_tf32(float* d, const uint32_t* a, const uint32_t* b) {
    asm volatile(
        "mma.sync.aligned.m16n8k8.row.col.f32.tf32.tf32.f32 "
        "{%0,%1,%2,%3}, {%4,%5,%6,%7}, {%8,%9}, {%0,%1,%2,%3};"
        : "+f"(d[0]), "+f"(d[1]), "+f"(d[2]), "+f"(d[3])
        : "r"(a[0]), "r"(a[1]), "r"(a[2]), "r"(a[3]), "r"(b[0]), "r"(b[1]));
}

// ---------------------------------------------------------------------------
// Kernel 1: SE gate. 16 threads per (b,n); thread j owns channels 4j..4j+3.
// 24 LDG.128 each, shuffle-reduce the 64->4 squeeze, no smem.
// ---------------------------------------------------------------------------
__global__ __launch_bounds__(256)
void gate_kernel(const float* __restrict__ xm,
                 const float* __restrict__ xl,
                 const float* __restrict__ w1,   // (4,64)
                 const float* __restrict__ w2)   // (64,4)
{
    const int tid = threadIdx.x;
    const int grp = tid >> 4;
    const int j   = tid & 15;
    const int bn  = blockIdx.x * 16 + grp;
    const int b   = bn >> 5;
    const int n   = bn & 31;

    const float4* pm = (const float4*)(xm
        + ((size_t)(b * (N_ENT * LEN_M) + n * LEN_M)) * C_DIM) + j;
    float4 s = make_float4(0.f, 0.f, 0.f, 0.f);
#pragma unroll
    for (int t = 0; t < LEN_M; t++) {
        float4 v = pm[t * 16];
        s.x += v.x; s.y += v.y; s.z += v.z; s.w += v.w;
    }
    const float4* pl = (const float4*)(xl
        + ((size_t)(b * (N_ENT * LEN_L) + n * LEN_L)) * C_DIM) + j;
#pragma unroll
    for (int t = 0; t < LEN_L; t++) {
        float4 v = pl[t * 16];
        s.x += v.x; s.y += v.y; s.z += v.z; s.w += v.w;
    }
    const float inv = 1.0f / 32.0f;
    s.x *= inv; s.y *= inv; s.z *= inv; s.w *= inv;

    float h[4];
#pragma unroll
    for (int i = 0; i < 4; i++) {
        float4 w = *(const float4*)(w1 + i * C_DIM + j * 4);
        h[i] = s.x * w.x + s.y * w.y + s.z * w.z + s.w * w.w;
    }
#pragma unroll
    for (int off = 8; off; off >>= 1)
#pragma unroll
        for (int i = 0; i < 4; i++)
            h[i] += __shfl_xor_sync(0xFFFFFFFFu, h[i], off);
#pragma unroll
    for (int i = 0; i < 4; i++) h[i] = fmaxf(h[i], 0.f);

    float4 g4;
#pragma unroll
    for (int q = 0; q < 4; q++) {
        int c = j * 4 + q;
        float4 w = *(const float4*)(w2 + c * 4);
        float z = h[0] * w.x + h[1] * w.y + h[2] * w.z + h[3] * w.w;
        ((float*)&g4)[q] = 1.0f / (1.0f + __expf(-z));
    }
    *(float4*)(g_gate + (size_t)bn * C_DIM + j * 4) = g4;
}

// ---------------------------------------------------------------------------
// Kernel 2: mma.sync tf32 GEMM.
// Smem layout (fragment-permuted): X[r][k] stored at [r*36 + (k%4)*8 + k/4].
// Thread (grp=lane>>2, tig=lane&3) then loads, per 2 k-steps, one LDS.128:
//   A row r:   AS[r*36 + tig*8 + ph*4 .. +3] = {a0(s0),a2(s0),a0(s1),a2(s1)}
//   A row r+8: same -> {a1,a3} pairs
//   B col n:   BS[n*36 + tig*8 + ph*4 .. +3] = {b0(s0),b1(s0),b0(s1),b1(s1)}
// Pitch 36 (36r = 4r mod 32) makes every 8-lane LDS.128 phase hit 8 distinct
// bank-quads -> conflict-free.
// ---------------------------------------------------------------------------
__global__ __launch_bounds__(128, 2)
void gemm_mma(const float* __restrict__ xm,
              const float* __restrict__ xl,
              const float* __restrict__ aw,    // (256, 2048) K-major
              const float* __restrict__ bias,
              float* __restrict__ out)
{
    extern __shared__ float sm[];
    float* AS = sm + SM_AS;
    float* BS = sm + SM_BS;
    float* GS = sm + SM_GS;

    const int tid  = threadIdx.x;
    const int lane = tid & 31;
    const int wid  = tid >> 5;
    const int tig  = lane & 3;
    const int grp  = lane >> 2;
    const int wrow = (wid >> 1) * 64;    // warp row offset in CTA tile
    const int wcol = (wid & 1) * 64;     // warp col offset in CTA tile
    const int row_base = blockIdx.x * 128;
    const int col_base = blockIdx.y * 128;

    // preload gates for this CTA's 128 rows (8192 floats)
    {
        const float4* gsrc = (const float4*)(g_gate + (size_t)row_base * C_DIM);
        float4* gdst = (float4*)GS;
#pragma unroll
        for (int i = 0; i < 16; i++) gdst[i * 128 + tid] = gsrc[i * 128 + tid];
    }

    float acc[4][8][4];
#pragma unroll
    for (int mt = 0; mt < 4; mt++)
#pragma unroll
        for (int nt = 0; nt < 8; nt++)
#pragma unroll
            for (int q = 0; q < 4; q++) acc[mt][nt][q] = 0.f;

    for (int kt = 0; kt < KT_TILES; kt++) {
        __syncthreads();   // previous compute done (also covers gate preload)

        // ---- A tile: 128 rows x 32 ch, gated, tf32, permuted ----
        const int t  = kt >> 1;
        const int c0 = (kt & 1) * 32;
#pragma unroll
        for (int i = 0; i < 8; i++) {
            int lin = i * 128 + tid;             // 1024 float4s
            int r = lin >> 3, c4 = lin & 7;
            int bn = row_base + r, b = bn >> 5, n = bn & 31;
            const float* src = (t < LEN_M)
                ? xm + (((size_t)(b * (N_ENT * LEN_M) + n * LEN_M + t)) * C_DIM + c0 + c4 * 4)
                : xl + (((size_t)(b * (N_ENT * LEN_L) + n * LEN_L + (t - LEN_M))) * C_DIM + c0 + c4 * 4);
            float4 v = *(const float4*)src;
            float4 g = *(const float4*)&GS[r * C_DIM + c0 + c4 * 4];
            float* ap = AS + r * PITCH + c4;
            ap[0]  = __uint_as_float(f2tf32(v.x * g.x));   // j=0
            ap[8]  = __uint_as_float(f2tf32(v.y * g.y));   // j=1
            ap[16] = __uint_as_float(f2tf32(v.z * g.z));   // j=2
            ap[24] = __uint_as_float(f2tf32(v.w * g.w));   // j=3
        }
        // ---- B tile: 128 outs x 32 k from align_w (skip pad cols) ----
        const int f0 = kt * 32 + (kt >= 32 ? 256 : 0);
        const float* wp = aw + (size_t)col_base * 2048 + f0;
#pragma unroll
        for (int i = 0; i < 8; i++) {
            int lin = i * 128 + tid;
            int n = lin >> 3, c4 = lin & 7;
            float4 v = *(const float4*)(wp + (size_t)n * 2048 + c4 * 4);
            float* bp = BS + n * PITCH + c4;
            bp[0]  = __uint_as_float(f2tf32(v.x));
            bp[8]  = __uint_as_float(f2tf32(v.y));
            bp[16] = __uint_as_float(f2tf32(v.z));
            bp[24] = __uint_as_float(f2tf32(v.w));
        }
        __syncthreads();

        // ---- compute: 2 phases x 2 k-steps ----
#pragma unroll
        for (int ph = 0; ph < 2; ph++) {
            uint32_t af[4][8];
#pragma unroll
            for (int mt = 0; mt < 4; mt++) {
                int r = wrow + mt * 16 + grp;
                *(uint4*)&af[mt][0] = *(const uint4*)&AS[r * PITCH + tig * 8 + ph * 4];
                *(uint4*)&af[mt][4] = *(const uint4*)&AS[(r + 8) * PITCH + tig * 8 + ph * 4];
            }
            uint32_t bf[8][4];
#pragma unroll
            for (int nt = 0; nt < 8; nt++) {
                int n = wcol + nt * 8 + grp;
                *(uint4*)&bf[nt][0] = *(const uint4*)&BS[n * PITCH + tig * 8 + ph * 4];
            }
#pragma unroll
            for (int s = 0; s < 2; s++) {
#pragma unroll
                for (int mt = 0; mt < 4; mt++) {
                    uint32_t a[4] = { af[mt][s * 2], af[mt][4 + s * 2],
                                      af[mt][1 + s * 2], af[mt][5 + s * 2] };
#pragma unroll
                    for (int nt = 0; nt < 8; nt++) {
                        uint32_t b[2] = { bf[nt][s * 2], bf[nt][s * 2 + 1] };
                        mma_tf32(acc[mt][nt], a, b);
                    }
                }
            }
        }
    }

    // ---- epilogue: bias + store (float2 per acc pair) ----
#pragma unroll
    for (int mt = 0; mt < 4; mt++) {
        int gr = row_base + wrow + mt * 16 + grp;
#pragma unroll
        for (int nt = 0; nt < 8; nt++) {
            int gc = col_base + wcol + nt * 8 + tig * 2;
            float2 bb = *(const float2*)&bias[gc];
            float2 v0; v0.x = acc[mt][nt][0] + bb.x; v0.y = acc[mt][nt][1] + bb.y;
            *(float2*)&out[(size_t)gr * OUT_DIM + gc] = v0;
            float2 v1; v1.x = acc[mt][nt][2] + bb.x; v1.y = acc[mt][nt][3] + bb.y;
            *(float2*)&out[(size_t)(gr + 8) * OUT_DIM + gc] = v1;
        }
    }
}

// ---------------------------------------------------------------------------
// Launch. Inputs: x_metric, x_log, y(unused), se_w1, se_w2, align_w, align_b.
// ---------------------------------------------------------------------------
extern "C" void kernel_launch(void* const* d_in, const int* in_sizes, int n_in,
                              void* d_out, int out_size)
{
    const float* xm = (const float*)d_in[0];
    const float* xl = (const float*)d_in[1];
    const float* w1 = (const float*)d_in[3];
    const float* w2 = (const float*)d_in[4];
    const float* aw = (const float*)d_in[5];
    const float* ab = (const float*)d_in[6];
    float* out = (float*)d_out;

    const int smem_bytes = SM_FLOATS * (int)sizeof(float);   // 69632
    cudaFuncSetAttribute(gemm_mma, cudaFuncAttributeMaxDynamicSharedMemorySize, smem_bytes);

    gate_kernel<<<ROWS_TOT / 16, 256>>>(xm, xl, w1, w2);
    dim3 grid(ROWS_TOT / 128, OUT_DIM / 128);
    gemm_mma<<<grid, 128, smem_bytes>>>(xm, xl, aw, ab, out);
}

// round 7
// speedup vs baseline: 2.9412x; 1.3751x over previous
#include <cuda_runtime.h>
#include <cstdint>

// ---------------------------------------------------------------------------
// FeatureIntegration: gather+pad -> SE gate -> GEMM (32768x1536 @ 1536x256)
// Round 7: R6 MMA core + pipelining.
//  - B: pre-converted tf32, fragment-permuted, XOR-swizzled tile images in
//    g_wt; GEMM streams them with 2-stage cp.async (no cvt/regs/STS for B).
//  - A: register-prefetch of next tile's LDGs overlapping current MMAs.
// ---------------------------------------------------------------------------

#define N_ENT    32
#define C_DIM    64
#define OUT_DIM  256
#define LEN_M    16
#define LEN_L    8
#define B_SZ     1024
#define ROWS_TOT (B_SZ * N_ENT)     // 32768

#define KT_TILES 48                 // 48 K-tiles of 32 floats = K_eff 1536
#define PITCH    36                 // AS row pitch (floats)

// smem float offsets
#define SM_AS  0                    // 128*36 = 4608
#define SM_BS0 4608                 // 128*32 = 4096
#define SM_BS1 8704
#define SM_GS  12800                // 128*64 = 8192
#define SM_FLOATS 20992             // 83968 bytes

__device__ float g_gate[(size_t)ROWS_TOT * C_DIM];          // 8.4 MB
__device__ float g_wt[2 * KT_TILES * 128 * 32];             // 1.5 MB tile images

__device__ __forceinline__ uint32_t f2tf32(float f) {
    uint32_t r;
    asm("cvt.rna.tf32.f32 %0, %1;" : "=r"(r) : "f"(f));
    return r;
}

__device__ __forceinline__ uint32_t smem_u32(const void* p) {
    uint32_t a;
    asm("{ .reg .u64 t; cvta.to.shared.u64 t, %1; cvt.u32.u64 %0, t; }"
        : "=r"(a) : "l"(p));
    return a;
}

__device__ __forceinline__ void cp16(uint32_t dst, const void* src) {
    asm volatile("cp.async.cg.shared.global [%0], [%1], 16;"
                 :: "r"(dst), "l"(src) : "memory");
}
#define CP_COMMIT() asm volatile("cp.async.commit_group;" ::: "memory")
#define CP_WAIT(N)  asm volatile("cp.async.wait_group %0;" :: "n"(N) : "memory")

__device__ __forceinline__ void mma_tf32(float* d, const uint32_t* a, const uint32_t* b) {
    asm volatile(
        "mma.sync.aligned.m16n8k8.row.col.f32.tf32.tf32.f32 "
        "{%0,%1,%2,%3}, {%4,%5,%6,%7}, {%8,%9}, {%0,%1,%2,%3};"
        : "+f"(d[0]), "+f"(d[1]), "+f"(d[2]), "+f"(d[3])
        : "r"(a[0]), "r"(a[1]), "r"(a[2]), "r"(a[3]), "r"(b[0]), "r"(b[1]));
}

// ---------------------------------------------------------------------------
// Kernel 1: SE gate (unchanged; R6 measured ~37us).
// ---------------------------------------------------------------------------
__global__ __launch_bounds__(256)
void gate_kernel(const float* __restrict__ xm,
                 const float* __restrict__ xl,
                 const float* __restrict__ w1,
                 const float* __restrict__ w2)
{
    const int tid = threadIdx.x;
    const int grp = tid >> 4;
    const int j   = tid & 15;
    const int bn  = blockIdx.x * 16 + grp;
    const int b   = bn >> 5;
    const int n   = bn & 31;

    const float4* pm = (const float4*)(xm
        + ((size_t)(b * (N_ENT * LEN_M) + n * LEN_M)) * C_DIM) + j;
    float4 s = make_float4(0.f, 0.f, 0.f, 0.f);
#pragma unroll
    for (int t = 0; t < LEN_M; t++) {
        float4 v = pm[t * 16];
        s.x += v.x; s.y += v.y; s.z += v.z; s.w += v.w;
    }
    const float4* pl = (const float4*)(xl
        + ((size_t)(b * (N_ENT * LEN_L) + n * LEN_L)) * C_DIM) + j;
#pragma unroll
    for (int t = 0; t < LEN_L; t++) {
        float4 v = pl[t * 16];
        s.x += v.x; s.y += v.y; s.z += v.z; s.w += v.w;
    }
    const float inv = 1.0f / 32.0f;
    s.x *= inv; s.y *= inv; s.z *= inv; s.w *= inv;

    float h[4];
#pragma unroll
    for (int i = 0; i < 4; i++) {
        float4 w = *(const float4*)(w1 + i * C_DIM + j * 4);
        h[i] = s.x * w.x + s.y * w.y + s.z * w.z + s.w * w.w;
    }
#pragma unroll
    for (int off = 8; off; off >>= 1)
#pragma unroll
        for (int i = 0; i < 4; i++)
            h[i] += __shfl_xor_sync(0xFFFFFFFFu, h[i], off);
#pragma unroll
    for (int i = 0; i < 4; i++) h[i] = fmaxf(h[i], 0.f);

    float4 g4;
#pragma unroll
    for (int q = 0; q < 4; q++) {
        int c = j * 4 + q;
        float4 w = *(const float4*)(w2 + c * 4);
        float z = h[0] * w.x + h[1] * w.y + h[2] * w.z + h[3] * w.w;
        ((float*)&g4)[q] = 1.0f / (1.0f + __expf(-z));
    }
    *(float4*)(g_gate + (size_t)bn * C_DIM + j * 4) = g4;
}

// ---------------------------------------------------------------------------
// Kernel 2: W prep. Builds per-(half h, tile kt) smem images: 128 rows x 32
// floats, fragment-permuted (pos p holds k=(p%8)*4+p/8) and XOR-swizzled
// (physical quad qp = logical quad q XOR (n&7)). GEMM copies them linearly.
// ---------------------------------------------------------------------------
__global__ __launch_bounds__(256)
void wprep_kernel(const float* __restrict__ aw)
{
    int gi = blockIdx.x * 256 + threadIdx.x;      // 98304 granules
    int qp = gi & 7;
    int n  = (gi >> 3) & 127;
    int hk = gi >> 10;                            // h*48 + kt
    int kt = hk % 48;
    int h  = hk / 48;
    int o  = h * 128 + n;
    int q  = qp ^ (n & 7);

    float4 v;
#pragma unroll
    for (int e = 0; e < 4; e++) {
        int pk = q * 4 + e;
        int k  = ((pk & 7) << 2) | (pk >> 3);
        int f  = kt * 32 + k + (kt >= 32 ? 256 : 0);
        ((float*)&v)[e] = __uint_as_float(f2tf32(aw[(size_t)o * 2048 + f]));
    }
    ((float4*)g_wt)[gi] = v;
}

// ---------------------------------------------------------------------------
// Kernel 3: pipelined mma.sync tf32 GEMM. CTA 128x128, 4 warps (64x64).
// ---------------------------------------------------------------------------
__global__ __launch_bounds__(128, 2)
void gemm_mma(const float* __restrict__ xm,
              const float* __restrict__ xl,
              const float* __restrict__ bias,
              float* __restrict__ out)
{
    extern __shared__ float sm[];
    float* AS = sm + SM_AS;
    float* GS = sm + SM_GS;
    const uint32_t sb = smem_u32(sm);

    const int tid  = threadIdx.x;
    const int lane = tid & 31;
    const int wid  = tid >> 5;
    const int tig  = lane & 3;
    const int grp  = lane >> 2;
    const int wrow = (wid >> 1) * 64;
    const int wcol = (wid & 1) * 64;
    const int row_base = blockIdx.x * 128;
    const int h        = blockIdx.y;              // col half
    const int col_base = h * 128;

    // gate preload (128 rows x 64)
    {
        const float4* gsrc = (const float4*)(g_gate + (size_t)row_base * C_DIM);
        float4* gdst = (float4*)GS;
#pragma unroll
        for (int i = 0; i < 16; i++) gdst[i * 128 + tid] = gsrc[i * 128 + tid];
    }

    // B tile 0 via cp.async
    const float4* wt_base = (const float4*)g_wt + (size_t)h * KT_TILES * 1024;
    {
        const float4* src = wt_base;              // tile 0
        uint32_t dst = sb + SM_BS0 * 4;
#pragma unroll
        for (int i = 0; i < 8; i++) {
            int gi = i * 128 + tid;
            cp16(dst + gi * 16, src + gi);
        }
        CP_COMMIT();
    }

    // A tile 0 prefetch into registers
    float4 va[8];
    {
        const int t = 0, c0 = 0;
#pragma unroll
        for (int i = 0; i < 8; i++) {
            int lin = i * 128 + tid;
            int r = lin >> 3, c4 = lin & 7;
            int bn = row_base + r, b = bn >> 5, n = bn & 31;
            const float* src = xm + (((size_t)(b * (N_ENT * LEN_M) + n * LEN_M + t)) * C_DIM + c0 + c4 * 4);
            va[i] = *(const float4*)src;
        }
    }

    float acc[4][8][4];
#pragma unroll
    for (int mt = 0; mt < 4; mt++)
#pragma unroll
        for (int nt = 0; nt < 8; nt++)
#pragma unroll
            for (int q = 0; q < 4; q++) acc[mt][nt][q] = 0.f;

    __syncthreads();   // GS ready

    for (int kt = 0; kt < KT_TILES; kt++) {
        const int cur = kt & 1;
        // ---- store A tile (gate + cvt + permuted scatter) ----
        const int c0 = (kt & 1) * 32;
#pragma unroll
        for (int i = 0; i < 8; i++) {
            int lin = i * 128 + tid;
            int r = lin >> 3, c4 = lin & 7;
            float4 v = va[i];
            float4 g = *(const float4*)&GS[r * C_DIM + c0 + c4 * 4];
            float* ap = AS + r * PITCH + c4;
            ap[0]  = __uint_as_float(f2tf32(v.x * g.x));
            ap[8]  = __uint_as_float(f2tf32(v.y * g.y));
            ap[16] = __uint_as_float(f2tf32(v.z * g.z));
            ap[24] = __uint_as_float(f2tf32(v.w * g.w));
        }
        // ---- cp.async B tile kt+1 ----
        if (kt + 1 < KT_TILES) {
            const float4* src = wt_base + (size_t)(kt + 1) * 1024;
            uint32_t dst = sb + (cur ? SM_BS0 : SM_BS1) * 4;
#pragma unroll
            for (int i = 0; i < 8; i++) {
                int gi = i * 128 + tid;
                cp16(dst + gi * 16, src + gi);
            }
            CP_COMMIT();
            CP_WAIT(1);       // tile kt's group complete
        } else {
            CP_WAIT(0);
        }
        __syncthreads();

        // ---- prefetch A tile kt+1 into registers (overlaps MMA) ----
        if (kt + 1 < KT_TILES) {
            const int t2 = (kt + 1) >> 1, c02 = ((kt + 1) & 1) * 32;
#pragma unroll
            for (int i = 0; i < 8; i++) {
                int lin = i * 128 + tid;
                int r = lin >> 3, c4 = lin & 7;
                int bn = row_base + r, b = bn >> 5, n = bn & 31;
                const float* src = (t2 < LEN_M)
                    ? xm + (((size_t)(b * (N_ENT * LEN_M) + n * LEN_M + t2)) * C_DIM + c02 + c4 * 4)
                    : xl + (((size_t)(b * (N_ENT * LEN_L) + n * LEN_L + (t2 - LEN_M))) * C_DIM + c02 + c4 * 4);
                va[i] = *(const float4*)src;
            }
        }

        // ---- compute (identical fragment math to R6) ----
        const float* BS = sm + (cur ? SM_BS1 : SM_BS0);
#pragma unroll
        for (int ph = 0; ph < 2; ph++) {
            uint32_t af[4][8];
#pragma unroll
            for (int mt = 0; mt < 4; mt++) {
                int r = wrow + mt * 16 + grp;
                *(uint4*)&af[mt][0] = *(const uint4*)&AS[r * PITCH + tig * 8 + ph * 4];
                *(uint4*)&af[mt][4] = *(const uint4*)&AS[(r + 8) * PITCH + tig * 8 + ph * 4];
            }
            uint32_t bf[8][4];
#pragma unroll
            for (int nt = 0; nt < 8; nt++) {
                int n = wcol + nt * 8 + grp;
                int qp = ((tig * 2 + ph) ^ (n & 7)) * 4;
                *(uint4*)&bf[nt][0] = *(const uint4*)&BS[n * 32 + qp];
            }
#pragma unroll
            for (int s = 0; s < 2; s++) {
#pragma unroll
                for (int mt = 0; mt < 4; mt++) {
                    uint32_t a[4] = { af[mt][s * 2], af[mt][4 + s * 2],
                                      af[mt][1 + s * 2], af[mt][5 + s * 2] };
#pragma unroll
                    for (int nt = 0; nt < 8; nt++) {
                        uint32_t b[2] = { bf[nt][s * 2], bf[nt][s * 2 + 1] };
                        mma_tf32(acc[mt][nt], a, b);
                    }
                }
            }
        }
        __syncthreads();
    }

    // ---- epilogue ----
#pragma unroll
    for (int mt = 0; mt < 4; mt++) {
        int gr = row_base + wrow + mt * 16 + grp;
#pragma unroll
        for (int nt = 0; nt < 8; nt++) {
            int gc = col_base + wcol + nt * 8 + tig * 2;
            float2 bb = *(const float2*)&bias[gc];
            float2 v0; v0.x = acc[mt][nt][0] + bb.x; v0.y = acc[mt][nt][1] + bb.y;
            *(float2*)&out[(size_t)gr * OUT_DIM + gc] = v0;
            float2 v1; v1.x = acc[mt][nt][2] + bb.x; v1.y = acc[mt][nt][3] + bb.y;
            *(float2*)&out[(size_t)(gr + 8) * OUT_DIM + gc] = v1;
        }
    }
}

// ---------------------------------------------------------------------------
// Launch. Inputs: x_metric, x_log, y(unused), se_w1, se_w2, align_w, align_b.
// ---------------------------------------------------------------------------
extern "C" void kernel_launch(void* const* d_in, const int* in_sizes, int n_in,
                              void* d_out, int out_size)
{
    const float* xm = (const float*)d_in[0];
    const float* xl = (const float*)d_in[1];
    const float* w1 = (const float*)d_in[3];
    const float* w2 = (const float*)d_in[4];
    const float* aw = (const float*)d_in[5];
    const float* ab = (const float*)d_in[6];
    float* out = (float*)d_out;

    const int smem_bytes = SM_FLOATS * (int)sizeof(float);   // 83968
    cudaFuncSetAttribute(gemm_mma, cudaFuncAttributeMaxDynamicSharedMemorySize, smem_bytes);

    gate_kernel<<<ROWS_TOT / 16, 256>>>(xm, xl, w1, w2);
    wprep_kernel<<<(2 * KT_TILES * 128 * 8) / 256, 256>>>(aw);
    dim3 grid(ROWS_TOT / 128, OUT_DIM / 128);
    gemm_mma<<<grid, 128, smem_bytes>>>(xm, xl, ab, out);
}